// round 3
// baseline (speedup 1.0000x reference)
#include <cuda_runtime.h>
#include <math.h>

#define HW 16384
#define IMW 128

// ---------------- scratch (single static device buffer, no allocations) -------------
#define OFF_XS   0ULL                          // [2,192,HW]
#define OFF_T1   3145728ULL                    // [2,192,HW]
#define OFF_Q    6291456ULL                    // [2,192,HW]
#define OFF_KVP  9437184ULL                    // [2,384,HW]
#define OFF_KV   22020096ULL                   // [2,384,HW]
#define OFF_YP   34603008ULL                   // [2,768,HW]
#define OFF_Y    59768832ULL                   // [2,768,HW]
#define OFF_M1   84934656ULL                   // [2,192]
#define OFF_MF   (OFF_M1 + 384ULL)
#define OFF_RQ   (OFF_MF + 384ULL)
#define OFF_RK   (OFF_RQ + 384ULL)
#define OFF_SP   (OFF_RK + 384ULL)             // [2,6,8,32,32]
#define OFF_ATT  (OFF_SP + 98304ULL)           // [2,6,32,32]
// tf32 transposed weights [ic][oc]
#define OFF_WQR  (OFF_ATT + 12288ULL)          // 144*192
#define OFF_WKVI (OFF_WQR + 27648ULL)          // 48*384
#define OFF_WPO  (OFF_WKVI + 18432ULL)         // 192*192
#define OFF_WPIN (OFF_WPO + 36864ULL)          // 192*768
#define OFF_WPOUT (OFF_WPIN + 147456ULL)       // 384*192
#define SCRATCH_TOTAL (OFF_WPOUT + 73728ULL)

__device__ float g_scratch[SCRATCH_TOTAL];

__device__ __forceinline__ unsigned tf32_rna(float f) {
    unsigned r; asm("cvt.rna.tf32.f32 %0, %1;" : "=r"(r) : "f"(f)); return r;
}

__device__ __forceinline__ void mma_tf32(float* d, const unsigned* a, unsigned b0, unsigned b1) {
    asm("mma.sync.aligned.m16n8k8.row.col.f32.tf32.tf32.f32 "
        "{%0,%1,%2,%3},{%4,%5,%6,%7},{%8,%9},{%0,%1,%2,%3};"
        : "+f"(d[0]), "+f"(d[1]), "+f"(d[2]), "+f"(d[3])
        : "r"(a[0]), "r"(a[1]), "r"(a[2]), "r"(a[3]), "r"(b0), "r"(b1));
}

// ---------------- prep: per-batch channel multipliers + k_v passthrough -------------
__global__ void prep_kernel(const float* __restrict__ kv,
                            const float* __restrict__ wkR,
                            const float* __restrict__ wkI,
                            const float* __restrict__ wffk,
                            float* __restrict__ m1, float* __restrict__ mf,
                            float* __restrict__ out_tail, int tail) {
    int t = blockIdx.x * blockDim.x + threadIdx.x;
    if (t < 384) {
        int b = t / 192, c = t % 192;
        float acc = 1.0f;
        if (c < 144) {
            const float* w = wkR + c * 192;
            const float* v = kv + b * 256;
            for (int i = 0; i < 192; i++) acc += w[i] * v[i];
        } else {
            const float* w = wkI + (c - 144) * 64;
            const float* v = kv + b * 256 + 192;
            for (int i = 0; i < 64; i++) acc += w[i] * v[i];
        }
        m1[t] = acc;
    } else if (t < 768) {
        int u = t - 384;
        int b = u / 192, c = u % 192;
        float acc = 1.0f;
        const float* w = wffk + c * 256;
        const float* v = kv + b * 256;
        for (int i = 0; i < 256; i++) acc += w[i] * v[i];
        mf[u] = acc;
    } else if (t - 768 < tail) {
        out_tail[t - 768] = kv[t - 768];
    }
}

// ---------------- weight transpose + tf32 round: W[oc][ic] -> Wt[ic][oc] ------------
__global__ void wprep_kernel(const float* __restrict__ w, int oc, int ic,
                             unsigned* __restrict__ wt) {
    int idx = blockIdx.x * blockDim.x + threadIdx.x;
    if (idx >= oc * ic) return;
    int o = idx / ic, i = idx % ic;
    wt[i * oc + o] = tf32_rna(w[idx]);
}

// ---------------- channel LayerNorm (over 192 ch) * per-(b,c) multiplier ------------
__global__ void ln_scale_kernel(const float* __restrict__ x,
                                const float* __restrict__ w, const float* __restrict__ bias,
                                const float* __restrict__ m, float* __restrict__ out) {
    int p = blockIdx.x * blockDim.x + threadIdx.x;
    int b  = p >> 14;
    int px = p & (HW - 1);
    const float* xb = x + (size_t)b * 192 * HW + px;
    float s = 0.f, s2 = 0.f;
    #pragma unroll 8
    for (int c = 0; c < 192; c++) { float v = xb[(size_t)c * HW]; s += v; s2 += v * v; }
    float mu   = s * (1.0f / 192.0f);
    float var  = s2 * (1.0f / 192.0f) - mu * mu;
    float rstd = rsqrtf(var + 1e-5f);
    float* ob = out + (size_t)b * 192 * HW + px;
    const float* mb = m + b * 192;
    #pragma unroll 8
    for (int c = 0; c < 192; c++) {
        float v = (xb[(size_t)c * HW] - mu) * rstd * w[c] + bias[c];
        ob[(size_t)c * HW] = v * mb[c];
    }
}

// ---------------- tensor-core 1x1 conv: out[b,oc,p] = Wt[ic][oc]^T @ in[b,icoff+ic,p]
// block: 64 oc x 256 px, 8 warps (2 oc x 4 px), warp m32 x n64, tf32 mma m16n8k8
__global__ void conv1x1_tc_kernel(const float* __restrict__ in, int ictot, int icoff, int ic,
                                  const unsigned* __restrict__ Wt, int octot,
                                  const float* __restrict__ res, float* __restrict__ out) {
    __shared__ unsigned sIn[16 * 264];   // [k][px], stride 264 (==8 mod 32)
    __shared__ unsigned sW[16 * 72];     // [k][oc], stride 72  (==8 mod 32)
    int b      = blockIdx.z;
    int ocbase = blockIdx.y * 64;
    int pbase  = blockIdx.x * 256;
    int t    = threadIdx.x;          // 256
    int wid  = t >> 5;
    int lane = t & 31;
    int g    = lane >> 2;            // groupID
    int tig  = lane & 3;             // thread-in-group
    int wm   = (wid & 1) * 32;
    int wn   = (wid >> 1) * 64;

    float d[2][8][4];
    #pragma unroll
    for (int mi = 0; mi < 2; mi++)
        #pragma unroll
        for (int ni = 0; ni < 8; ni++)
            #pragma unroll
            for (int r = 0; r < 4; r++) d[mi][ni][r] = 0.f;

    const float* inb = in + ((size_t)b * ictot + icoff) * HW + pbase;

    for (int k0 = 0; k0 < ic; k0 += 16) {
        #pragma unroll
        for (int l = 0; l < 16; l++)       // 16 x 256 input tile, tf32 rounded
            sIn[l * 264 + t] = tf32_rna(inb[(size_t)(k0 + l) * HW + t]);
        #pragma unroll
        for (int l = 0; l < 4; l++) {      // 16 x 64 weight tile (already tf32)
            int idx = l * 256 + t;
            int r = idx >> 6, cc = idx & 63;
            sW[r * 72 + cc] = Wt[(size_t)(k0 + r) * octot + ocbase + cc];
        }
        __syncthreads();
        #pragma unroll
        for (int k8 = 0; k8 < 2; k8++) {
            unsigned a[2][4];
            #pragma unroll
            for (int mi = 0; mi < 2; mi++) {
                int m = wm + mi * 16 + g;
                a[mi][0] = sW[(k8 * 8 + tig) * 72 + m];
                a[mi][1] = sW[(k8 * 8 + tig) * 72 + m + 8];
                a[mi][2] = sW[(k8 * 8 + tig + 4) * 72 + m];
                a[mi][3] = sW[(k8 * 8 + tig + 4) * 72 + m + 8];
            }
            #pragma unroll
            for (int ni = 0; ni < 8; ni++) {
                int px = wn + ni * 8 + g;
                unsigned b0 = sIn[(k8 * 8 + tig) * 264 + px];
                unsigned b1 = sIn[(k8 * 8 + tig + 4) * 264 + px];
                mma_tf32(d[0][ni], a[0], b0, b1);
                mma_tf32(d[1][ni], a[1], b0, b1);
            }
        }
        __syncthreads();
    }

    #pragma unroll
    for (int mi = 0; mi < 2; mi++) {
        #pragma unroll
        for (int ni = 0; ni < 8; ni++) {
            int oc0 = ocbase + wm + mi * 16 + g;
            int px  = pbase + wn + ni * 8 + tig * 2;
            size_t off0 = ((size_t)b * octot + oc0) * HW + px;
            size_t off1 = off0 + (size_t)8 * HW;
            float2 r0 = make_float2(d[mi][ni][0], d[mi][ni][1]);
            float2 r1 = make_float2(d[mi][ni][2], d[mi][ni][3]);
            if (res) {
                float2 e0 = *reinterpret_cast<const float2*>(res + off0);
                float2 e1 = *reinterpret_cast<const float2*>(res + off1);
                r0.x += e0.x; r0.y += e0.y; r1.x += e1.x; r1.y += e1.y;
            }
            *reinterpret_cast<float2*>(out + off0) = r0;
            *reinterpret_cast<float2*>(out + off1) = r1;
        }
    }
}

// ---------------- depthwise 3x3, zero pad ------------------------------------------
__global__ void dwconv_kernel(const float* __restrict__ in, const float* __restrict__ w,
                              int C, float* __restrict__ out) {
    size_t idx = (size_t)blockIdx.x * blockDim.x + threadIdx.x;
    size_t total = (size_t)2 * C * HW;
    if (idx >= total) return;
    int x = (int)(idx & 127);
    int y = (int)((idx >> 7) & 127);
    int c = (int)((idx >> 14) % C);
    const float* wp = w + c * 9;
    const float* ip = in + (idx - (idx & (HW - 1)));
    float acc = 0.f;
    #pragma unroll
    for (int ky = 0; ky < 3; ky++) {
        int yy = y + ky - 1;
        if (yy < 0 || yy > 127) continue;
        #pragma unroll
        for (int kx = 0; kx < 3; kx++) {
            int xx = x + kx - 1;
            if (xx < 0 || xx > 127) continue;
            acc += ip[yy * IMW + xx] * wp[ky * 3 + kx];
        }
    }
    out[idx] = acc;
}

// ---------------- reciprocal L2 norm over HW per (b, channel) row ------------------
__global__ void rnorm_kernel(const float* __restrict__ t, int chtot, int coff,
                             float* __restrict__ rn) {
    int row = blockIdx.x;
    int b = row / 192, c = row % 192;
    const float* p = t + ((size_t)b * chtot + coff + c) * HW;
    float s = 0.f;
    for (int i = threadIdx.x; i < HW; i += blockDim.x) { float v = p[i]; s += v * v; }
    __shared__ float red[8];
    #pragma unroll
    for (int o = 16; o; o >>= 1) s += __shfl_down_sync(0xffffffffu, s, o);
    if ((threadIdx.x & 31) == 0) red[threadIdx.x >> 5] = s;
    __syncthreads();
    if (threadIdx.x < 32) {
        s = (threadIdx.x < 8) ? red[threadIdx.x] : 0.f;
        #pragma unroll
        for (int o = 4; o; o >>= 1) s += __shfl_down_sync(0xffffffffu, s, o);
        if (threadIdx.x == 0) rn[row] = 1.0f / fmaxf(sqrtf(s), 1e-12f);
    }
}

// ---------------- q@k^T partials ----------------------------------------------------
__global__ void qk_kernel(const float* __restrict__ q, const float* __restrict__ kv,
                          float* __restrict__ Sp) {
    int pc = blockIdx.x, hh = blockIdx.y, b = blockIdx.z;
    const float* qb = q  + ((size_t)b * 192 + hh * 32) * HW + pc * 2048;
    const float* kb = kv + ((size_t)b * 384 + hh * 32) * HW + pc * 2048;
    __shared__ float sq[32 * 33];
    __shared__ float sk[32 * 33];
    int t = threadIdx.x;
    int i = t & 31, jg = t >> 5;
    float acc[4] = {0.f, 0.f, 0.f, 0.f};
    for (int p0 = 0; p0 < 2048; p0 += 32) {
        #pragma unroll
        for (int l = 0; l < 4; l++) {
            int idx = t + l * 256;
            int r = idx >> 5, cc = idx & 31;
            sq[r * 33 + cc] = qb[(size_t)r * HW + p0 + cc];
            sk[r * 33 + cc] = kb[(size_t)r * HW + p0 + cc];
        }
        __syncthreads();
        #pragma unroll
        for (int p = 0; p < 32; p++) {
            float a = sq[i * 33 + p];
            #pragma unroll
            for (int j = 0; j < 4; j++) acc[j] += a * sk[(jg * 4 + j) * 33 + p];
        }
        __syncthreads();
    }
    float* sp = Sp + (((size_t)(b * 6 + hh) * 8 + pc) * 1024);
    #pragma unroll
    for (int j = 0; j < 4; j++) sp[i * 32 + jg * 4 + j] = acc[j];
}

// ---------------- softmax over last dim ---------------------------------------------
__global__ void softmax_kernel(const float* __restrict__ Sp, const float* __restrict__ rq,
                               const float* __restrict__ rk, const float* __restrict__ temp,
                               float* __restrict__ attn) {
    int bh = blockIdx.x;
    int b = bh / 6, hh = bh % 6;
    int t = threadIdx.x;
    int i = t >> 5, j = t & 31;
    const float* sp = Sp + (size_t)bh * 8192 + i * 32 + j;
    float s = 0.f;
    #pragma unroll
    for (int pc = 0; pc < 8; pc++) s += sp[pc * 1024];
    s *= rq[b * 192 + hh * 32 + i] * rk[b * 192 + hh * 32 + j] * temp[hh];
    float mx = s;
    #pragma unroll
    for (int o = 16; o; o >>= 1) mx = fmaxf(mx, __shfl_xor_sync(0xffffffffu, mx, o));
    float e = expf(s - mx);
    float sum = e;
    #pragma unroll
    for (int o = 16; o; o >>= 1) sum += __shfl_xor_sync(0xffffffffu, sum, o);
    attn[(size_t)bh * 1024 + i * 32 + j] = e / sum;
}

// ---------------- out = attn @ v ----------------------------------------------------
__global__ void av_kernel(const float* __restrict__ attn, const float* __restrict__ kv,
                          float* __restrict__ out) {
    int b = blockIdx.z, hh = blockIdx.y;
    int p = blockIdx.x * 256 + threadIdx.x;
    __shared__ float sA[1024];
    for (int l = threadIdx.x; l < 1024; l += 256)
        sA[l] = attn[(size_t)(b * 6 + hh) * 1024 + l];
    __syncthreads();
    const float* vb = kv + ((size_t)b * 384 + 192 + hh * 32) * HW + p;
    float v[32];
    #pragma unroll
    for (int e = 0; e < 32; e++) v[e] = vb[(size_t)e * HW];
    float* ob = out + ((size_t)b * 192 + hh * 32) * HW + p;
    #pragma unroll
    for (int i = 0; i < 32; i++) {
        float acc = 0.f;
        #pragma unroll
        for (int e = 0; e < 32; e++) acc += sA[i * 32 + e] * v[e];
        ob[(size_t)i * HW] = acc;
    }
}

// ---------------- gelu(y1) * y2 -----------------------------------------------------
__global__ void gelu_gate_kernel(const float* __restrict__ y, float* __restrict__ g) {
    size_t idx = (size_t)blockIdx.x * blockDim.x + threadIdx.x;
    if (idx >= (size_t)2 * 384 * HW) return;
    size_t b = idx / ((size_t)384 * HW);
    size_t r = idx % ((size_t)384 * HW);
    const float* yb = y + b * 768 * HW;
    float a  = yb[r];
    float g2 = yb[r + (size_t)384 * HW];
    float ge = 0.5f * a * (1.0f + erff(a * 0.70710678118654752f));
    g[idx] = ge * g2;
}

// ====================================================================================
extern "C" void kernel_launch(void* const* d_in, const int* in_sizes, int n_in,
                              void* d_out, int out_size) {
    const float* x      = (const float*)d_in[0];
    const float* k_v    = (const float*)d_in[1];
    const float* ln1_w  = (const float*)d_in[2];
    const float* ln1_b  = (const float*)d_in[3];
    const float* temp   = (const float*)d_in[4];
    const float* w_kR   = (const float*)d_in[5];
    const float* w_kI   = (const float*)d_in[6];
    const float* w_qR   = (const float*)d_in[7];
    const float* w_qdw  = (const float*)d_in[8];
    const float* w_kvI  = (const float*)d_in[9];
    const float* w_kvdw = (const float*)d_in[10];
    const float* w_po   = (const float*)d_in[11];
    const float* ln2_w  = (const float*)d_in[12];
    const float* ln2_b  = (const float*)d_in[13];
    const float* w_ffk  = (const float*)d_in[14];
    const float* w_pin  = (const float*)d_in[15];
    const float* w_dw   = (const float*)d_in[16];
    const float* w_pout = (const float*)d_in[17];
    float* out = (float*)d_out;

    float* scratch = nullptr;
    cudaGetSymbolAddress((void**)&scratch, g_scratch);
    float* xs  = scratch + OFF_XS;
    float* t1  = scratch + OFF_T1;
    float* q   = scratch + OFF_Q;
    float* kvp = scratch + OFF_KVP;
    float* kvb = scratch + OFF_KV;
    float* yp  = scratch + OFF_YP;
    float* yb  = scratch + OFF_Y;
    float* m1  = scratch + OFF_M1;
    float* mf  = scratch + OFF_MF;
    float* rq  = scratch + OFF_RQ;
    float* rk  = scratch + OFF_RK;
    float* Sp  = scratch + OFF_SP;
    float* att = scratch + OFF_ATT;
    unsigned* wqr   = (unsigned*)(scratch + OFF_WQR);
    unsigned* wkvi  = (unsigned*)(scratch + OFF_WKVI);
    unsigned* wpo   = (unsigned*)(scratch + OFF_WPO);
    unsigned* wpin  = (unsigned*)(scratch + OFF_WPIN);
    unsigned* wpout = (unsigned*)(scratch + OFF_WPOUT);

    int tail = out_size - 6291456;
    if (tail < 0) tail = 0;
    if (tail > 512) tail = 512;

    // prep: channel multipliers + k_v passthrough + tf32 transposed weights
    prep_kernel<<<5, 256>>>(k_v, w_kR, w_kI, w_ffk, m1, mf, out + 6291456, tail);
    wprep_kernel<<<(192 * 144 + 255) / 256, 256>>>(w_qR, 192, 144, wqr);
    wprep_kernel<<<(384 * 48 + 255) / 256, 256>>>(w_kvI, 384, 48, wkvi);
    wprep_kernel<<<(192 * 192 + 255) / 256, 256>>>(w_po, 192, 192, wpo);
    wprep_kernel<<<(768 * 192 + 255) / 256, 256>>>(w_pin, 768, 192, wpin);
    wprep_kernel<<<(192 * 384 + 255) / 256, 256>>>(w_pout, 192, 384, wpout);

    // ---- attention branch ----
    ln_scale_kernel<<<128, 256>>>(x, ln1_w, ln1_b, m1, xs);
    conv1x1_tc_kernel<<<dim3(128, 3, 2), 256>>>(xs, 192, 0, 144, wqr, 192, nullptr, t1);
    conv1x1_tc_kernel<<<dim3(128, 6, 2), 256>>>(xs, 192, 144, 48, wkvi, 384, nullptr, kvp);
    dwconv_kernel<<<(2 * 192 * HW) / 256, 256>>>(t1, w_qdw, 192, q);
    dwconv_kernel<<<(2 * 384 * HW) / 256, 256>>>(kvp, w_kvdw, 384, kvb);
    rnorm_kernel<<<384, 256>>>(q, 192, 0, rq);
    rnorm_kernel<<<384, 256>>>(kvb, 384, 0, rk);
    qk_kernel<<<dim3(8, 6, 2), 256>>>(q, kvb, Sp);
    softmax_kernel<<<12, 1024>>>(Sp, rq, rk, temp, att);
    av_kernel<<<dim3(64, 6, 2), 256>>>(att, kvb, t1);
    conv1x1_tc_kernel<<<dim3(128, 3, 2), 256>>>(t1, 192, 0, 192, wpo, 192, x, out);

    // ---- GDFN feed-forward ----
    ln_scale_kernel<<<128, 256>>>(out, ln2_w, ln2_b, mf, xs);
    conv1x1_tc_kernel<<<dim3(128, 12, 2), 256>>>(xs, 192, 0, 192, wpin, 768, nullptr, yp);
    dwconv_kernel<<<(2 * 768 * HW) / 256, 256>>>(yp, w_dw, 768, yb);
    gelu_gate_kernel<<<(2 * 384 * HW) / 256, 256>>>(yb, kvp);
    conv1x1_tc_kernel<<<dim3(128, 3, 2), 256>>>(kvp, 384, 0, 384, wpout, 192, out, out);
}

// round 5
// speedup vs baseline: 1.2062x; 1.2062x over previous
#include <cuda_runtime.h>
#include <stdint.h>
#include <math.h>

#define HW 16384

// ---------------- helpers ----------------
__device__ __forceinline__ uint32_t smem_u32(const void* p) {
    uint32_t a;
    asm("{ .reg .u64 t; cvta.to.shared.u64 t, %1; cvt.u32.u64 %0, t; }" : "=r"(a) : "l"(p));
    return a;
}
__device__ __forceinline__ uint32_t tf32_rna(float f) {
    uint32_t r; asm("cvt.rna.tf32.f32 %0, %1;" : "=r"(r) : "f"(f)); return r;
}
__device__ __forceinline__ void cp_async16(uint32_t dst, const float* src) {
    asm volatile("cp.async.cg.shared.global [%0], [%1], 16;" :: "r"(dst), "l"(src));
}
#define CP_COMMIT() asm volatile("cp.async.commit_group;" ::: "memory")
#define CP_WAIT0()  asm volatile("cp.async.wait_group 0;" ::: "memory")

__device__ __forceinline__ void mma_tf32(float* d, const uint32_t* a, uint32_t b0, uint32_t b1) {
    asm("mma.sync.aligned.m16n8k8.row.col.f32.tf32.tf32.f32 "
        "{%0,%1,%2,%3},{%4,%5,%6,%7},{%8,%9},{%0,%1,%2,%3};"
        : "+f"(d[0]), "+f"(d[1]), "+f"(d[2]), "+f"(d[3])
        : "r"(a[0]), "r"(a[1]), "r"(a[2]), "r"(a[3]), "r"(b0), "r"(b1));
}

// ---------------- scratch (floats, fully disjoint) ----------------
#define OFF_XS    0ULL            // [2,192,HW]
#define OFF_T1    6291456ULL      // [2,192,HW]
#define OFF_Q     12582912ULL     // [2,192,HW]
#define OFF_KVP   18874368ULL     // [2,384,HW]
#define OFF_KVB   31457280ULL     // [2,384,HW]
#define OFF_YP    44040192ULL     // [2,768,HW]
#define OFF_YB    69206016ULL     // [2,768,HW]
#define OFF_M1    94371840ULL
#define OFF_MF    94372224ULL
#define OFF_RQ    94372608ULL
#define OFF_RK    94372992ULL
#define OFF_SP    94373376ULL     // [2,6,8,32,32]
#define OFF_ATT   94471680ULL     // [2,6,32,32]
#define OFF_WQ    94483968ULL     // 192*144
#define OFF_WKV   94511616ULL     // 384*48
#define OFF_WPO   94530048ULL     // 192*192
#define OFF_WPIN  94566912ULL     // 768*192
#define OFF_WPOUT 94714368ULL     // 192*384
#define SCRATCH_TOTAL 94788096ULL
__device__ float g_scratch[SCRATCH_TOTAL];

// ---------------- prep: per-batch channel multipliers + k_v tail --------------------
__global__ void prep_kernel(const float* __restrict__ kv, const float* __restrict__ wkR,
                            const float* __restrict__ wkI, const float* __restrict__ wffk,
                            float* __restrict__ m1, float* __restrict__ mf,
                            float* __restrict__ out_tail, int tail) {
    int t = blockIdx.x * blockDim.x + threadIdx.x;
    if (t < 384) {
        int b = t / 192, c = t % 192;
        float acc = 1.0f;
        if (c < 144) {
            const float* w = wkR + c * 192; const float* v = kv + b * 256;
            for (int i = 0; i < 192; i++) acc += w[i] * v[i];
        } else {
            const float* w = wkI + (c - 144) * 64; const float* v = kv + b * 256 + 192;
            for (int i = 0; i < 64; i++) acc += w[i] * v[i];
        }
        m1[t] = acc;
    } else if (t < 768) {
        int u = t - 384; int b = u / 192, c = u % 192;
        float acc = 1.0f;
        const float* w = wffk + c * 256; const float* v = kv + b * 256;
        for (int i = 0; i < 256; i++) acc += w[i] * v[i];
        mf[u] = acc;
    } else if (t - 768 < tail) {
        out_tail[t - 768] = kv[t - 768];
    }
}

// ------- pack weights W[oc][ic] into tf32 B-fragment order -------
// pack[ocb][kc][ni][lane][j]: lane=(g<<2)|tig; oc=ocb*64+ni*8+g; k=kc*16+tig+(j&1)*4+(j>>1)*8
__global__ void wpack_kernel(const float* __restrict__ W, int octot, int ic,
                             float* __restrict__ pack) {
    int idx = blockIdx.x * 256 + threadIdx.x;
    if (idx >= octot * ic) return;
    int j = idx & 3, lane = (idx >> 2) & 31, ni = (idx >> 7) & 7;
    int NKC = ic >> 4;
    int kc = (idx >> 10) % NKC;
    int ocb = (idx >> 10) / NKC;
    int g = lane >> 2, tig = lane & 3;
    int oc = ocb * 64 + ni * 8 + g;
    int k = kc * 16 + tig + (j & 1) * 4 + (j >> 1) * 8;
    pack[idx] = __uint_as_float(tf32_rna(W[(size_t)oc * ic + k]));
}

// ------- channel LayerNorm * per-(b,c) multiplier, tf32-rounded output -------
__global__ void ln_scale_kernel(const float* __restrict__ x, const float* __restrict__ w,
                                const float* __restrict__ bias, const float* __restrict__ m,
                                float* __restrict__ out) {
    int p = blockIdx.x * blockDim.x + threadIdx.x;
    int b = p >> 14, px = p & (HW - 1);
    const float* xb = x + (size_t)b * 192 * HW + px;
    float s = 0.f, s2 = 0.f;
    #pragma unroll 8
    for (int c = 0; c < 192; c++) { float v = xb[(size_t)c * HW]; s += v; s2 += v * v; }
    float mu = s * (1.0f / 192.0f);
    float rstd = rsqrtf(s2 * (1.0f / 192.0f) - mu * mu + 1e-5f);
    float* ob = out + (size_t)b * 192 * HW + px;
    const float* mb = m + b * 192;
    #pragma unroll 8
    for (int c = 0; c < 192; c++) {
        float v = (xb[(size_t)c * HW] - mu) * rstd * w[c] + bias[c];
        ob[(size_t)c * HW] = __uint_as_float(tf32_rna(v * mb[c]));
    }
}

// ------- tf32 mma.sync conv1x1: out[b,oc,px] = W[oc,K] @ in[b,icoff+K,px] (+res) -----
// block: 256 px x 64 oc; 8 warps each 32px(m) x 64oc(n); weights smem-resident (packed)
__global__ void __launch_bounds__(256) conv_mma_kernel(
        const float* __restrict__ in, int ictot, int icoff, int NKC,
        const float* __restrict__ wpack, int octot, int tpc,
        const float* __restrict__ res, float* __restrict__ out) {
    extern __shared__ float sm[];
    float* sW = sm;                                   // NKC*1024 floats (packed frags)
    uint32_t* sInu = (uint32_t*)(sm + NKC * 1024);    // 2 x [16][260]
    uint32_t sInb = smem_u32(sInu);
    int tid = threadIdx.x, wid = tid >> 5, lane = tid & 31;
    int g = lane >> 2, tig = lane & 3;
    int ocbase = blockIdx.y * 64;

    {   // resident weights for this 64-oc slice
        const float4* gw = (const float4*)(wpack + (size_t)blockIdx.y * NKC * 1024);
        float4* sw4 = (float4*)sW;
        for (int i = tid; i < NKC * 256; i += 256) sw4[i] = gw[i];
    }
    __syncthreads();

    for (int t = 0; t < tpc; t++) {
        int pxg = (blockIdx.x * tpc + t) * 256;
        int b = pxg >> 14, pxb = pxg & (HW - 1);
        const float* gin = in + ((size_t)b * ictot + icoff) * HW + pxb;

        // prefetch k-chunk 0 -> buf 0
        #pragma unroll
        for (int it = 0; it < 4; it++) {
            int idx = it * 256 + tid;
            int row = idx >> 6, c4 = (idx & 63) << 2;
            cp_async16(sInb + (uint32_t)(row * 260 + c4) * 4u, gin + (size_t)row * HW + c4);
        }
        CP_COMMIT();

        float d[2][8][4];
        #pragma unroll
        for (int mi = 0; mi < 2; mi++)
            #pragma unroll
            for (int ni = 0; ni < 8; ni++)
                #pragma unroll
                for (int r = 0; r < 4; r++) d[mi][ni][r] = 0.f;

        for (int kc = 0; kc < NKC; kc++) {
            CP_WAIT0();
            __syncthreads();
            if (kc + 1 < NKC) {           // prefetch next chunk into other buffer
                const float* src = gin + (size_t)(kc + 1) * 16 * HW;
                uint32_t dstb = sInb + (uint32_t)((kc + 1) & 1) * 16640u;
                #pragma unroll
                for (int it = 0; it < 4; it++) {
                    int idx = it * 256 + tid;
                    int row = idx >> 6, c4 = (idx & 63) << 2;
                    cp_async16(dstb + (uint32_t)(row * 260 + c4) * 4u, src + (size_t)row * HW + c4);
                }
                CP_COMMIT();
            }
            const uint32_t* sbuf = sInu + (kc & 1) * 4160;
            uint32_t a[2][2][4];
            #pragma unroll
            for (int mi = 0; mi < 2; mi++) {
                int m0 = wid * 32 + mi * 16 + g;
                #pragma unroll
                for (int k8 = 0; k8 < 2; k8++) {
                    int kr = k8 * 8;
                    a[mi][k8][0] = sbuf[(kr + tig) * 260 + m0];
                    a[mi][k8][1] = sbuf[(kr + tig) * 260 + m0 + 8];
                    a[mi][k8][2] = sbuf[(kr + tig + 4) * 260 + m0];
                    a[mi][k8][3] = sbuf[(kr + tig + 4) * 260 + m0 + 8];
                }
            }
            const float4* wrow = (const float4*)(sW + kc * 1024) + lane;
            #pragma unroll
            for (int ni = 0; ni < 8; ni++) {
                float4 bv = wrow[ni * 32];
                uint32_t b0 = __float_as_uint(bv.x), b1 = __float_as_uint(bv.y);
                uint32_t b2 = __float_as_uint(bv.z), b3 = __float_as_uint(bv.w);
                mma_tf32(d[0][ni], a[0][0], b0, b1);
                mma_tf32(d[1][ni], a[1][0], b0, b1);
                mma_tf32(d[0][ni], a[0][1], b2, b3);
                mma_tf32(d[1][ni], a[1][1], b2, b3);
            }
        }
        // epilogue: d0=(px g, oc 2tig) d1=(g,2tig+1) d2=(g+8,2tig) d3=(g+8,2tig+1)
        #pragma unroll
        for (int mi = 0; mi < 2; mi++) {
            int px0 = pxb + wid * 32 + mi * 16 + g;
            #pragma unroll
            for (int ni = 0; ni < 8; ni++) {
                int oc0 = ocbase + ni * 8 + tig * 2;
                size_t o00 = ((size_t)b * octot + oc0) * HW + px0;
                size_t o01 = o00 + HW;
                float v0 = d[mi][ni][0], v1 = d[mi][ni][1];
                float v2 = d[mi][ni][2], v3 = d[mi][ni][3];
                if (res) {
                    v0 += res[o00]; v1 += res[o01];
                    v2 += res[o00 + 8]; v3 += res[o01 + 8];
                }
                out[o00] = v0; out[o01] = v1;
                out[o00 + 8] = v2; out[o01 + 8] = v3;
            }
        }
        __syncthreads();   // protect smem buffers before next tile's prefetch
    }
}

// ---------------- depthwise 3x3, zero pad -------------------------------------------
__global__ void dwconv_kernel(const float* __restrict__ in, const float* __restrict__ w,
                              int C, float* __restrict__ out) {
    size_t idx = (size_t)blockIdx.x * blockDim.x + threadIdx.x;
    if (idx >= (size_t)2 * C * HW) return;
    int x = (int)(idx & 127);
    int y = (int)((idx >> 7) & 127);
    int c = (int)((idx >> 14) % C);
    const float* wp = w + c * 9;
    const float* ip = in + (idx - (idx & (HW - 1)));
    float acc = 0.f;
    #pragma unroll
    for (int ky = 0; ky < 3; ky++) {
        int yy = y + ky - 1;
        if (yy < 0 || yy > 127) continue;
        #pragma unroll
        for (int kx = 0; kx < 3; kx++) {
            int xx = x + kx - 1;
            if (xx < 0 || xx > 127) continue;
            acc += ip[yy * 128 + xx] * wp[ky * 3 + kx];
        }
    }
    out[idx] = acc;
}

// ---------------- reciprocal L2 norm over HW per (b, channel) -----------------------
__global__ void rnorm_kernel(const float* __restrict__ t, int chtot, int coff,
                             float* __restrict__ rn) {
    int row = blockIdx.x;
    int b = row / 192, c = row % 192;
    const float* p = t + ((size_t)b * chtot + coff + c) * HW;
    float s = 0.f;
    for (int i = threadIdx.x; i < HW; i += blockDim.x) { float v = p[i]; s += v * v; }
    __shared__ float red[8];
    #pragma unroll
    for (int o = 16; o; o >>= 1) s += __shfl_down_sync(0xffffffffu, s, o);
    if ((threadIdx.x & 31) == 0) red[threadIdx.x >> 5] = s;
    __syncthreads();
    if (threadIdx.x < 32) {
        s = (threadIdx.x < 8) ? red[threadIdx.x] : 0.f;
        #pragma unroll
        for (int o = 4; o; o >>= 1) s += __shfl_down_sync(0xffffffffu, s, o);
        if (threadIdx.x == 0) rn[row] = 1.0f / fmaxf(sqrtf(s), 1e-12f);
    }
}

// ---------------- q@k^T partials -----------------------------------------------------
__global__ void qk_kernel(const float* __restrict__ q, const float* __restrict__ kv,
                          float* __restrict__ Sp) {
    int pc = blockIdx.x, hh = blockIdx.y, b = blockIdx.z;
    const float* qb = q  + ((size_t)b * 192 + hh * 32) * HW + pc * 2048;
    const float* kb = kv + ((size_t)b * 384 + hh * 32) * HW + pc * 2048;
    __shared__ float sq[32 * 33];
    __shared__ float sk[32 * 33];
    int t = threadIdx.x;
    int i = t & 31, jg = t >> 5;
    float acc[4] = {0.f, 0.f, 0.f, 0.f};
    for (int p0 = 0; p0 < 2048; p0 += 32) {
        #pragma unroll
        for (int l = 0; l < 4; l++) {
            int idx = t + l * 256;
            int r = idx >> 5, cc = idx & 31;
            sq[r * 33 + cc] = qb[(size_t)r * HW + p0 + cc];
            sk[r * 33 + cc] = kb[(size_t)r * HW + p0 + cc];
        }
        __syncthreads();
        #pragma unroll
        for (int p = 0; p < 32; p++) {
            float a = sq[i * 33 + p];
            #pragma unroll
            for (int j = 0; j < 4; j++) acc[j] += a * sk[(jg * 4 + j) * 33 + p];
        }
        __syncthreads();
    }
    float* sp = Sp + (((size_t)(b * 6 + hh) * 8 + pc) * 1024);
    #pragma unroll
    for (int j = 0; j < 4; j++) sp[i * 32 + jg * 4 + j] = acc[j];
}

// ---------------- softmax -------------------------------------------------------------
__global__ void softmax_kernel(const float* __restrict__ Sp, const float* __restrict__ rq,
                               const float* __restrict__ rk, const float* __restrict__ temp,
                               float* __restrict__ attn) {
    int bh = blockIdx.x;
    int b = bh / 6, hh = bh % 6;
    int t = threadIdx.x;
    int i = t >> 5, j = t & 31;
    const float* sp = Sp + (size_t)bh * 8192 + i * 32 + j;
    float s = 0.f;
    #pragma unroll
    for (int pc = 0; pc < 8; pc++) s += sp[pc * 1024];
    s *= rq[b * 192 + hh * 32 + i] * rk[b * 192 + hh * 32 + j] * temp[hh];
    float mx = s;
    #pragma unroll
    for (int o = 16; o; o >>= 1) mx = fmaxf(mx, __shfl_xor_sync(0xffffffffu, mx, o));
    float e = expf(s - mx);
    float sum = e;
    #pragma unroll
    for (int o = 16; o; o >>= 1) sum += __shfl_xor_sync(0xffffffffu, sum, o);
    attn[(size_t)bh * 1024 + i * 32 + j] = e / sum;
}

// ---------------- out = attn @ v (tf32-rounded: feeds conv po) -----------------------
__global__ void av_kernel(const float* __restrict__ attn, const float* __restrict__ kv,
                          float* __restrict__ out) {
    int b = blockIdx.z, hh = blockIdx.y;
    int p = blockIdx.x * 256 + threadIdx.x;
    __shared__ float sA[1024];
    for (int l = threadIdx.x; l < 1024; l += 256)
        sA[l] = attn[(size_t)(b * 6 + hh) * 1024 + l];
    __syncthreads();
    const float* vb = kv + ((size_t)b * 384 + 192 + hh * 32) * HW + p;
    float v[32];
    #pragma unroll
    for (int e = 0; e < 32; e++) v[e] = vb[(size_t)e * HW];
    float* ob = out + ((size_t)b * 192 + hh * 32) * HW + p;
    #pragma unroll
    for (int i = 0; i < 32; i++) {
        float acc = 0.f;
        #pragma unroll
        for (int e = 0; e < 32; e++) acc += sA[i * 32 + e] * v[e];
        ob[(size_t)i * HW] = __uint_as_float(tf32_rna(acc));
    }
}

// ---------------- gelu(y1)*y2 (tf32-rounded: feeds conv pout) ------------------------
__global__ void gelu_gate_kernel(const float* __restrict__ y, float* __restrict__ g) {
    size_t idx = (size_t)blockIdx.x * blockDim.x + threadIdx.x;
    if (idx >= (size_t)2 * 384 * HW) return;
    size_t b = idx / ((size_t)384 * HW);
    size_t r = idx % ((size_t)384 * HW);
    const float* yb = y + b * 768 * HW;
    float a  = yb[r];
    float g2 = yb[r + (size_t)384 * HW];
    float ge = 0.5f * a * (1.0f + erff(a * 0.70710678118654752f));
    g[idx] = __uint_as_float(tf32_rna(ge * g2));
}

// ====================================================================================
extern "C" void kernel_launch(void* const* d_in, const int* in_sizes, int n_in,
                              void* d_out, int out_size) {
    const float* x      = (const float*)d_in[0];
    const float* k_v    = (const float*)d_in[1];
    const float* ln1_w  = (const float*)d_in[2];
    const float* ln1_b  = (const float*)d_in[3];
    const float* temp   = (const float*)d_in[4];
    const float* w_kR   = (const float*)d_in[5];
    const float* w_kI   = (const float*)d_in[6];
    const float* w_qR   = (const float*)d_in[7];
    const float* w_qdw  = (const float*)d_in[8];
    const float* w_kvI  = (const float*)d_in[9];
    const float* w_kvdw = (const float*)d_in[10];
    const float* w_po   = (const float*)d_in[11];
    const float* ln2_w  = (const float*)d_in[12];
    const float* ln2_b  = (const float*)d_in[13];
    const float* w_ffk  = (const float*)d_in[14];
    const float* w_pin  = (const float*)d_in[15];
    const float* w_dw   = (const float*)d_in[16];
    const float* w_pout = (const float*)d_in[17];
    float* out = (float*)d_out;

    float* sc = nullptr;
    cudaGetSymbolAddress((void**)&sc, g_scratch);
    float* xs   = sc + OFF_XS;
    float* t1   = sc + OFF_T1;
    float* q    = sc + OFF_Q;
    float* kvp  = sc + OFF_KVP;
    float* kvb  = sc + OFF_KVB;
    float* yp   = sc + OFF_YP;
    float* ybuf = sc + OFF_YB;
    float* m1   = sc + OFF_M1;
    float* mf   = sc + OFF_MF;
    float* rq   = sc + OFF_RQ;
    float* rk   = sc + OFF_RK;
    float* Sp   = sc + OFF_SP;
    float* att  = sc + OFF_ATT;
    float* wq    = sc + OFF_WQ;
    float* wkv   = sc + OFF_WKV;
    float* wpo   = sc + OFF_WPO;
    float* wpin  = sc + OFF_WPIN;
    float* wpout = sc + OFF_WPOUT;

    cudaFuncSetAttribute(conv_mma_kernel, cudaFuncAttributeMaxDynamicSharedMemorySize, 131584);
    auto smb = [](int NKC) { return (size_t)NKC * 4096 + 33280; };

    int tail = out_size - 6291456;
    if (tail < 0) tail = 0;
    if (tail > 512) tail = 512;

    // prep + packed weights
    prep_kernel<<<5, 256>>>(k_v, w_kR, w_kI, w_ffk, m1, mf, out + 6291456, tail);
    wpack_kernel<<<108, 256>>>(w_qR, 192, 144, wq);
    wpack_kernel<<<72, 256>>>(w_kvI, 384, 48, wkv);
    wpack_kernel<<<144, 256>>>(w_po, 192, 192, wpo);
    wpack_kernel<<<576, 256>>>(w_pin, 768, 192, wpin);
    wpack_kernel<<<288, 256>>>(w_pout, 192, 384, wpout);

    // attention branch
    ln_scale_kernel<<<128, 256>>>(x, ln1_w, ln1_b, m1, xs);
    conv_mma_kernel<<<dim3(64, 3), 256, smb(9)>>>(xs, 192, 0, 9, wq, 192, 2, nullptr, t1);
    conv_mma_kernel<<<dim3(64, 6), 256, smb(3)>>>(xs, 192, 144, 3, wkv, 384, 2, nullptr, kvp);
    dwconv_kernel<<<(2 * 192 * HW) / 256, 256>>>(t1, w_qdw, 192, q);
    dwconv_kernel<<<(2 * 384 * HW) / 256, 256>>>(kvp, w_kvdw, 384, kvb);
    rnorm_kernel<<<384, 256>>>(q, 192, 0, rq);
    rnorm_kernel<<<384, 256>>>(kvb, 384, 0, rk);
    qk_kernel<<<dim3(8, 6, 2), 256>>>(q, kvb, Sp);
    softmax_kernel<<<12, 1024>>>(Sp, rq, rk, temp, att);
    av_kernel<<<dim3(64, 6, 2), 256>>>(att, kvb, t1);
    conv_mma_kernel<<<dim3(64, 3), 256, smb(12)>>>(t1, 192, 0, 12, wpo, 192, 2, x, out);

    // GDFN feed-forward
    ln_scale_kernel<<<128, 256>>>(out, ln2_w, ln2_b, mf, xs);
    conv_mma_kernel<<<dim3(64, 12), 256, smb(12)>>>(xs, 192, 0, 12, wpin, 768, 2, nullptr, yp);
    dwconv_kernel<<<(2 * 768 * HW) / 256, 256>>>(yp, w_dw, 768, ybuf);
    gelu_gate_kernel<<<(2 * 384 * HW) / 256, 256>>>(ybuf, kvp);
    conv_mma_kernel<<<dim3(64, 3), 256, smb(24)>>>(kvp, 384, 0, 24, wpout, 192, 2, out, out);
}

// round 6
// speedup vs baseline: 1.5528x; 1.2874x over previous
#include <cuda_runtime.h>
#include <stdint.h>
#include <math.h>

#define HW 16384

// ---------------- helpers ----------------
__device__ __forceinline__ uint32_t smem_u32(const void* p) {
    uint32_t a;
    asm("{ .reg .u64 t; cvta.to.shared.u64 t, %1; cvt.u32.u64 %0, t; }" : "=r"(a) : "l"(p));
    return a;
}
__device__ __forceinline__ uint32_t tf32_rna(float f) {
    uint32_t r; asm("cvt.rna.tf32.f32 %0, %1;" : "=r"(r) : "f"(f)); return r;
}
__device__ __forceinline__ void cp_async16(uint32_t dst, const float* src) {
    asm volatile("cp.async.cg.shared.global [%0], [%1], 16;" :: "r"(dst), "l"(src));
}
#define CP_COMMIT() asm volatile("cp.async.commit_group;" ::: "memory")
#define CP_WAIT0()  asm volatile("cp.async.wait_group 0;" ::: "memory")
#define CP_WAIT1()  asm volatile("cp.async.wait_group 1;" ::: "memory")

__device__ __forceinline__ void mma_tf32(float* d, const uint32_t* a, uint32_t b0, uint32_t b1) {
    asm("mma.sync.aligned.m16n8k8.row.col.f32.tf32.tf32.f32 "
        "{%0,%1,%2,%3},{%4,%5,%6,%7},{%8,%9},{%0,%1,%2,%3};"
        : "+f"(d[0]), "+f"(d[1]), "+f"(d[2]), "+f"(d[3])
        : "r"(a[0]), "r"(a[1]), "r"(a[2]), "r"(a[3]), "r"(b0), "r"(b1));
}

// ---------------- scratch (floats, fully disjoint) ----------------
#define OFF_XS    0ULL            // [2,192,HW]
#define OFF_T1    6291456ULL      // [2,192,HW]
#define OFF_Q     12582912ULL     // [2,192,HW]
#define OFF_KVP   18874368ULL     // [2,384,HW]
#define OFF_KVB   31457280ULL     // [2,384,HW]
#define OFF_YP    44040192ULL     // [2,768,HW]
#define OFF_PAD   69206016ULL     // pad-kernel target (unused data)
#define OFF_M1    94371840ULL
#define OFF_MF    94372224ULL
#define OFF_RQ    94372608ULL
#define OFF_RK    94372992ULL
#define OFF_SP    94373376ULL     // [2,6,8,32,32]
#define OFF_ATT   94471680ULL     // [2,6,32,32]
#define OFF_WQ    94483968ULL     // 192*144
#define OFF_WKV   94511616ULL     // 384*48
#define OFF_WPO   94530048ULL     // 192*192
#define OFF_WPIN  94566912ULL     // 768*192
#define OFF_WPOUT 94714368ULL     // 192*384
#define SCRATCH_TOTAL 94788096ULL
__device__ float g_scratch[SCRATCH_TOTAL];

// ---------------- prep: per-batch channel multipliers + k_v tail --------------------
__global__ void prep_kernel(const float* __restrict__ kv, const float* __restrict__ wkR,
                            const float* __restrict__ wkI, const float* __restrict__ wffk,
                            float* __restrict__ m1, float* __restrict__ mf,
                            float* __restrict__ out_tail, int tail) {
    int t = blockIdx.x * blockDim.x + threadIdx.x;
    if (t < 384) {
        int b = t / 192, c = t % 192;
        float acc = 1.0f;
        if (c < 144) {
            const float* w = wkR + c * 192; const float* v = kv + b * 256;
            for (int i = 0; i < 192; i++) acc += w[i] * v[i];
        } else {
            const float* w = wkI + (c - 144) * 64; const float* v = kv + b * 256 + 192;
            for (int i = 0; i < 64; i++) acc += w[i] * v[i];
        }
        m1[t] = acc;
    } else if (t < 768) {
        int u = t - 384; int b = u / 192, c = u % 192;
        float acc = 1.0f;
        const float* w = wffk + c * 256; const float* v = kv + b * 256;
        for (int i = 0; i < 256; i++) acc += w[i] * v[i];
        mf[u] = acc;
    } else if (t - 768 < tail) {
        out_tail[t - 768] = kv[t - 768];
    }
}

// ------- pack weights into tf32 B-fragment order (same mapping as before) -------
__device__ __forceinline__ void pack_one(const float* __restrict__ W, int octot, int ic,
                                         float* __restrict__ pack, int idx) {
    int j = idx & 3, lane = (idx >> 2) & 31, ni = (idx >> 7) & 7;
    int NKC = ic >> 4;
    int kc = (idx >> 10) % NKC;
    int ocb = (idx >> 10) / NKC;
    int g = lane >> 2, tig = lane & 3;
    int oc = ocb * 64 + ni * 8 + g;
    int k = kc * 16 + tig + (j & 1) * 4 + (j >> 1) * 8;
    pack[idx] = __uint_as_float(tf32_rna(W[(size_t)oc * ic + k]));
}

__global__ void wpack_all_kernel(const float* __restrict__ wq, const float* __restrict__ wkv,
                                 const float* __restrict__ wpo, const float* __restrict__ wpin,
                                 const float* __restrict__ wpout,
                                 float* __restrict__ pq, float* __restrict__ pkv,
                                 float* __restrict__ ppo, float* __restrict__ ppin,
                                 float* __restrict__ ppout) {
    int idx = blockIdx.x * 256 + threadIdx.x;
    if (idx < 27648)        pack_one(wq,    192, 144, pq,    idx);
    else if (idx < 46080)   pack_one(wkv,   384,  48, pkv,   idx - 27648);
    else if (idx < 82944)   pack_one(wpo,   192, 192, ppo,   idx - 46080);
    else if (idx < 230400)  pack_one(wpin,  768, 192, ppin,  idx - 82944);
    else if (idx < 304128)  pack_one(wpout, 192, 384, ppout, idx - 230400);
}

// ------- tiny pad kernel (launch-index alignment for ncu) -------
__global__ void pad_kernel(float* __restrict__ p) {
    if (threadIdx.x == 0) p[blockIdx.x] = 0.f;
}

// ------- channel LayerNorm * per-(b,c) multiplier, tf32-rounded output -------
__global__ void ln_scale_kernel(const float* __restrict__ x, const float* __restrict__ w,
                                const float* __restrict__ bias, const float* __restrict__ m,
                                float* __restrict__ out) {
    int p = blockIdx.x * blockDim.x + threadIdx.x;
    int b = p >> 14, px = p & (HW - 1);
    const float* xb = x + (size_t)b * 192 * HW + px;
    float s = 0.f, s2 = 0.f;
    #pragma unroll 8
    for (int c = 0; c < 192; c++) { float v = xb[(size_t)c * HW]; s += v; s2 += v * v; }
    float mu = s * (1.0f / 192.0f);
    float rstd = rsqrtf(s2 * (1.0f / 192.0f) - mu * mu + 1e-5f);
    float* ob = out + (size_t)b * 192 * HW + px;
    const float* mb = m + b * 192;
    #pragma unroll 8
    for (int c = 0; c < 192; c++) {
        float v = (xb[(size_t)c * HW] - mu) * rstd * w[c] + bias[c];
        ob[(size_t)c * HW] = __uint_as_float(tf32_rna(v * mb[c]));
    }
}

// ------- tf32 mma.sync conv1x1, warp-autonomous mainloop (no block barriers) --------
// block: 256 px x 64 oc; warp = 32 px x 64 oc with private double-buffered input smem
__global__ void __launch_bounds__(256) conv_mma_kernel(
        const float* __restrict__ in, int ictot, int icoff, int NKC,
        const float* __restrict__ wpack, int octot, int tpc,
        const float* __restrict__ res, float* __restrict__ out) {
    extern __shared__ float sm[];
    float* sW = sm;                              // NKC*1024 floats (packed B frags)
    float* sIn = sm + NKC * 1024;                // 8 warps x 2 bufs x [16][40]
    uint32_t sInb = smem_u32(sIn);
    int tid = threadIdx.x, wid = tid >> 5, lane = tid & 31;
    int g = lane >> 2, tig = lane & 3;
    int ocbase = blockIdx.y * 64;

    {   // resident packed weights for this 64-oc slice
        const float4* gw = (const float4*)(wpack + (size_t)blockIdx.y * NKC * 1024);
        float4* sw4 = (float4*)sW;
        for (int i = tid; i < NKC * 256; i += 256) sw4[i] = gw[i];
    }
    __syncthreads();

    float* wIn = sIn + wid * 1280;
    uint32_t wInb = sInb + (uint32_t)wid * 5120u;

    for (int t = 0; t < tpc; t++) {
        int pxg = (blockIdx.x * tpc + t) * 256;
        int b = pxg >> 14, pxb = pxg & (HW - 1);
        const float* gin = in + ((size_t)b * ictot + icoff) * HW + pxb + wid * 32;

        // prefetch chunk 0 -> buf 0 (warp-private)
        #pragma unroll
        for (int i = 0; i < 4; i++) {
            int u = lane + 32 * i;
            int r = u >> 3, c16 = u & 7;
            cp_async16(wInb + (uint32_t)(r * 160 + c16 * 16), gin + (size_t)r * HW + c16 * 4);
        }
        CP_COMMIT();

        float d[2][8][4];
        #pragma unroll
        for (int mi = 0; mi < 2; mi++)
            #pragma unroll
            for (int ni = 0; ni < 8; ni++)
                #pragma unroll
                for (int r = 0; r < 4; r++) d[mi][ni][r] = 0.f;

        for (int kc = 0; kc < NKC; kc++) {
            if (kc + 1 < NKC) {       // prefetch next chunk into other warp-buffer
                const float* src = gin + (size_t)(kc + 1) * 16 * HW;
                uint32_t dstb = wInb + (uint32_t)((kc + 1) & 1) * 2560u;
                #pragma unroll
                for (int i = 0; i < 4; i++) {
                    int u = lane + 32 * i;
                    int r = u >> 3, c16 = u & 7;
                    cp_async16(dstb + (uint32_t)(r * 160 + c16 * 16), src + (size_t)r * HW + c16 * 4);
                }
                CP_COMMIT();
                CP_WAIT1();
            } else {
                CP_WAIT0();
            }
            __syncwarp();

            const float* sbuf = wIn + (kc & 1) * 640;
            uint32_t a[2][2][4];
            #pragma unroll
            for (int mi = 0; mi < 2; mi++) {
                int m0 = mi * 16 + g;
                #pragma unroll
                for (int k8 = 0; k8 < 2; k8++) {
                    int kr = k8 * 8;
                    a[mi][k8][0] = __float_as_uint(sbuf[(kr + tig) * 40 + m0]);
                    a[mi][k8][1] = __float_as_uint(sbuf[(kr + tig) * 40 + m0 + 8]);
                    a[mi][k8][2] = __float_as_uint(sbuf[(kr + tig + 4) * 40 + m0]);
                    a[mi][k8][3] = __float_as_uint(sbuf[(kr + tig + 4) * 40 + m0 + 8]);
                }
            }
            const float4* wrow = (const float4*)(sW + kc * 1024) + lane;
            #pragma unroll
            for (int ni = 0; ni < 8; ni++) {
                float4 bv = wrow[ni * 32];
                uint32_t b0 = __float_as_uint(bv.x), b1 = __float_as_uint(bv.y);
                uint32_t b2 = __float_as_uint(bv.z), b3 = __float_as_uint(bv.w);
                mma_tf32(d[0][ni], a[0][0], b0, b1);
                mma_tf32(d[1][ni], a[1][0], b0, b1);
                mma_tf32(d[0][ni], a[0][1], b2, b3);
                mma_tf32(d[1][ni], a[1][1], b2, b3);
            }
        }

        // epilogue (warp-local, no sync): d0=(px g,oc 2tig) d1=(g,+1) d2=(g+8,2tig) d3=(g+8,+1)
        #pragma unroll
        for (int mi = 0; mi < 2; mi++) {
            int px0 = pxb + wid * 32 + mi * 16 + g;
            #pragma unroll
            for (int ni = 0; ni < 8; ni++) {
                int oc0 = ocbase + ni * 8 + tig * 2;
                size_t o00 = ((size_t)b * octot + oc0) * HW + px0;
                size_t o01 = o00 + HW;
                float v0 = d[mi][ni][0], v1 = d[mi][ni][1];
                float v2 = d[mi][ni][2], v3 = d[mi][ni][3];
                if (res) {
                    v0 += res[o00]; v1 += res[o01];
                    v2 += res[o00 + 8]; v3 += res[o01 + 8];
                }
                out[o00] = v0; out[o01] = v1;
                out[o00 + 8] = v2; out[o01 + 8] = v3;
            }
        }
    }
}

// ---------------- depthwise 3x3, zero pad -------------------------------------------
__global__ void dwconv_kernel(const float* __restrict__ in, const float* __restrict__ w,
                              int C, float* __restrict__ out) {
    size_t idx = (size_t)blockIdx.x * blockDim.x + threadIdx.x;
    if (idx >= (size_t)2 * C * HW) return;
    int x = (int)(idx & 127);
    int y = (int)((idx >> 7) & 127);
    int c = (int)((idx >> 14) % C);
    const float* wp = w + c * 9;
    const float* ip = in + (idx - (idx & (HW - 1)));
    float acc = 0.f;
    #pragma unroll
    for (int ky = 0; ky < 3; ky++) {
        int yy = y + ky - 1;
        if (yy < 0 || yy > 127) continue;
        #pragma unroll
        for (int kx = 0; kx < 3; kx++) {
            int xx = x + kx - 1;
            if (xx < 0 || xx > 127) continue;
            acc += ip[yy * 128 + xx] * wp[ky * 3 + kx];
        }
    }
    out[idx] = acc;
}

// --------- fused depthwise 3x3 (768ch) + gelu gate -> tf32-rounded output ----------
__global__ void dwconv_gelu_kernel(const float* __restrict__ in, const float* __restrict__ w,
                                   float* __restrict__ out) {
    size_t idx = (size_t)blockIdx.x * blockDim.x + threadIdx.x;
    if (idx >= (size_t)2 * 384 * HW) return;
    int x = (int)(idx & 127);
    int y = (int)((idx >> 7) & 127);
    int c = (int)((idx >> 14) % 384);
    int b = (int)(idx / ((size_t)384 * HW));
    const float* ip1 = in + ((size_t)b * 768 + c) * HW;
    const float* ip2 = ip1 + (size_t)384 * HW;
    const float* w1 = w + c * 9;
    const float* w2 = w + (c + 384) * 9;
    float a1 = 0.f, a2 = 0.f;
    #pragma unroll
    for (int ky = 0; ky < 3; ky++) {
        int yy = y + ky - 1;
        if (yy < 0 || yy > 127) continue;
        #pragma unroll
        for (int kx = 0; kx < 3; kx++) {
            int xx = x + kx - 1;
            if (xx < 0 || xx > 127) continue;
            float v1 = ip1[yy * 128 + xx], v2 = ip2[yy * 128 + xx];
            a1 += v1 * w1[ky * 3 + kx];
            a2 += v2 * w2[ky * 3 + kx];
        }
    }
    float ge = 0.5f * a1 * (1.0f + erff(a1 * 0.70710678118654752f));
    out[idx] = __uint_as_float(tf32_rna(ge * a2));
}

// ---------------- reciprocal L2 norm over HW per (b, channel) -----------------------
__global__ void rnorm_kernel(const float* __restrict__ t, int chtot, int coff,
                             float* __restrict__ rn) {
    int row = blockIdx.x;
    int b = row / 192, c = row % 192;
    const float* p = t + ((size_t)b * chtot + coff + c) * HW;
    float s = 0.f;
    for (int i = threadIdx.x; i < HW; i += blockDim.x) { float v = p[i]; s += v * v; }
    __shared__ float red[8];
    #pragma unroll
    for (int o = 16; o; o >>= 1) s += __shfl_down_sync(0xffffffffu, s, o);
    if ((threadIdx.x & 31) == 0) red[threadIdx.x >> 5] = s;
    __syncthreads();
    if (threadIdx.x < 32) {
        s = (threadIdx.x < 8) ? red[threadIdx.x] : 0.f;
        #pragma unroll
        for (int o = 4; o; o >>= 1) s += __shfl_down_sync(0xffffffffu, s, o);
        if (threadIdx.x == 0) rn[row] = 1.0f / fmaxf(sqrtf(s), 1e-12f);
    }
}

// ---------------- q@k^T partials -----------------------------------------------------
__global__ void qk_kernel(const float* __restrict__ q, const float* __restrict__ kv,
                          float* __restrict__ Sp) {
    int pc = blockIdx.x, hh = blockIdx.y, b = blockIdx.z;
    const float* qb = q  + ((size_t)b * 192 + hh * 32) * HW + pc * 2048;
    const float* kb = kv + ((size_t)b * 384 + hh * 32) * HW + pc * 2048;
    __shared__ float sq[32 * 33];
    __shared__ float sk[32 * 33];
    int t = threadIdx.x;
    int i = t & 31, jg = t >> 5;
    float acc[4] = {0.f, 0.f, 0.f, 0.f};
    for (int p0 = 0; p0 < 2048; p0 += 32) {
        #pragma unroll
        for (int l = 0; l < 4; l++) {
            int idx = t + l * 256;
            int r = idx >> 5, cc = idx & 31;
            sq[r * 33 + cc] = qb[(size_t)r * HW + p0 + cc];
            sk[r * 33 + cc] = kb[(size_t)r * HW + p0 + cc];
        }
        __syncthreads();
        #pragma unroll
        for (int p = 0; p < 32; p++) {
            float a = sq[i * 33 + p];
            #pragma unroll
            for (int j = 0; j < 4; j++) acc[j] += a * sk[(jg * 4 + j) * 33 + p];
        }
        __syncthreads();
    }
    float* sp = Sp + (((size_t)(b * 6 + hh) * 8 + pc) * 1024);
    #pragma unroll
    for (int j = 0; j < 4; j++) sp[i * 32 + jg * 4 + j] = acc[j];
}

// ---------------- softmax -------------------------------------------------------------
__global__ void softmax_kernel(const float* __restrict__ Sp, const float* __restrict__ rq,
                               const float* __restrict__ rk, const float* __restrict__ temp,
                               float* __restrict__ attn) {
    int bh = blockIdx.x;
    int b = bh / 6, hh = bh % 6;
    int t = threadIdx.x;
    int i = t >> 5, j = t & 31;
    const float* sp = Sp + (size_t)bh * 8192 + i * 32 + j;
    float s = 0.f;
    #pragma unroll
    for (int pc = 0; pc < 8; pc++) s += sp[pc * 1024];
    s *= rq[b * 192 + hh * 32 + i] * rk[b * 192 + hh * 32 + j] * temp[hh];
    float mx = s;
    #pragma unroll
    for (int o = 16; o; o >>= 1) mx = fmaxf(mx, __shfl_xor_sync(0xffffffffu, mx, o));
    float e = expf(s - mx);
    float sum = e;
    #pragma unroll
    for (int o = 16; o; o >>= 1) sum += __shfl_xor_sync(0xffffffffu, sum, o);
    attn[(size_t)bh * 1024 + i * 32 + j] = e / sum;
}

// ---------------- out = attn @ v (tf32-rounded: feeds conv po) -----------------------
__global__ void av_kernel(const float* __restrict__ attn, const float* __restrict__ kv,
                          float* __restrict__ out) {
    int b = blockIdx.z, hh = blockIdx.y;
    int p = blockIdx.x * 256 + threadIdx.x;
    __shared__ float sA[1024];
    for (int l = threadIdx.x; l < 1024; l += 256)
        sA[l] = attn[(size_t)(b * 6 + hh) * 1024 + l];
    __syncthreads();
    const float* vb = kv + ((size_t)b * 384 + 192 + hh * 32) * HW + p;
    float v[32];
    #pragma unroll
    for (int e = 0; e < 32; e++) v[e] = vb[(size_t)e * HW];
    float* ob = out + ((size_t)b * 192 + hh * 32) * HW + p;
    #pragma unroll
    for (int i = 0; i < 32; i++) {
        float acc = 0.f;
        #pragma unroll
        for (int e = 0; e < 32; e++) acc += sA[i * 32 + e] * v[e];
        ob[(size_t)i * HW] = __uint_as_float(tf32_rna(acc));
    }
}

// ====================================================================================
extern "C" void kernel_launch(void* const* d_in, const int* in_sizes, int n_in,
                              void* d_out, int out_size) {
    const float* x      = (const float*)d_in[0];
    const float* k_v    = (const float*)d_in[1];
    const float* ln1_w  = (const float*)d_in[2];
    const float* ln1_b  = (const float*)d_in[3];
    const float* temp   = (const float*)d_in[4];
    const float* w_kR   = (const float*)d_in[5];
    const float* w_kI   = (const float*)d_in[6];
    const float* w_qR   = (const float*)d_in[7];
    const float* w_qdw  = (const float*)d_in[8];
    const float* w_kvI  = (const float*)d_in[9];
    const float* w_kvdw = (const float*)d_in[10];
    const float* w_po   = (const float*)d_in[11];
    const float* ln2_w  = (const float*)d_in[12];
    const float* ln2_b  = (const float*)d_in[13];
    const float* w_ffk  = (const float*)d_in[14];
    const float* w_pin  = (const float*)d_in[15];
    const float* w_dw   = (const float*)d_in[16];
    const float* w_pout = (const float*)d_in[17];
    float* out = (float*)d_out;

    float* sc = nullptr;
    cudaGetSymbolAddress((void**)&sc, g_scratch);
    float* xs   = sc + OFF_XS;
    float* t1   = sc + OFF_T1;
    float* q    = sc + OFF_Q;
    float* kvp  = sc + OFF_KVP;
    float* kvb  = sc + OFF_KVB;
    float* yp   = sc + OFF_YP;
    float* padt = sc + OFF_PAD;
    float* m1   = sc + OFF_M1;
    float* mf   = sc + OFF_MF;
    float* rq   = sc + OFF_RQ;
    float* rk   = sc + OFF_RK;
    float* Sp   = sc + OFF_SP;
    float* att  = sc + OFF_ATT;
    float* wq    = sc + OFF_WQ;
    float* wkv   = sc + OFF_WKV;
    float* wpo   = sc + OFF_WPO;
    float* wpin  = sc + OFF_WPIN;
    float* wpout = sc + OFF_WPOUT;

    cudaFuncSetAttribute(conv_mma_kernel, cudaFuncAttributeMaxDynamicSharedMemorySize, 139264);
    auto smb = [](int NKC) { return (size_t)NKC * 4096 + 40960; };

    int tail = out_size - 6291456;
    if (tail < 0) tail = 0;
    if (tail > 512) tail = 512;

    // 0-4: prep, packed weights, LN1, pads (so launch #5 = conv_q for ncu)
    prep_kernel<<<5, 256>>>(k_v, w_kR, w_kI, w_ffk, m1, mf, out + 6291456, tail);
    wpack_all_kernel<<<1188, 256>>>(w_qR, w_kvI, w_po, w_pin, w_pout,
                                    wq, wkv, wpo, wpin, wpout);
    ln_scale_kernel<<<128, 256>>>(x, ln1_w, ln1_b, m1, xs);
    pad_kernel<<<1, 32>>>(padt);
    pad_kernel<<<1, 32>>>(padt + 8);

    // attention branch
    conv_mma_kernel<<<dim3(64, 3), 256, smb(9)>>>(xs, 192, 0, 9, wq, 192, 2, nullptr, t1);
    conv_mma_kernel<<<dim3(64, 6), 256, smb(3)>>>(xs, 192, 144, 3, wkv, 384, 2, nullptr, kvp);
    dwconv_kernel<<<(2 * 192 * HW) / 256, 256>>>(t1, w_qdw, 192, q);
    dwconv_kernel<<<(2 * 384 * HW) / 256, 256>>>(kvp, w_kvdw, 384, kvb);
    rnorm_kernel<<<384, 256>>>(q, 192, 0, rq);
    rnorm_kernel<<<384, 256>>>(kvb, 384, 0, rk);
    qk_kernel<<<dim3(8, 6, 2), 256>>>(q, kvb, Sp);
    softmax_kernel<<<12, 1024>>>(Sp, rq, rk, temp, att);
    av_kernel<<<dim3(64, 6, 2), 256>>>(att, kvb, t1);
    conv_mma_kernel<<<dim3(64, 3), 256, smb(12)>>>(t1, 192, 0, 12, wpo, 192, 2, x, out);

    // GDFN feed-forward
    ln_scale_kernel<<<128, 256>>>(out, ln2_w, ln2_b, mf, xs);
    conv_mma_kernel<<<dim3(16, 12), 256, smb(12)>>>(xs, 192, 0, 12, wpin, 768, 8, nullptr, yp);
    dwconv_gelu_kernel<<<(2 * 384 * HW) / 256, 256>>>(yp, w_dw, kvp);
    conv_mma_kernel<<<dim3(64, 3), 256, smb(24)>>>(kvp, 384, 0, 24, wpout, 192, 2, out, out);
}

// round 7
// speedup vs baseline: 1.8581x; 1.1966x over previous
#include <cuda_runtime.h>
#include <cuda_bf16.h>
#include <stdint.h>
#include <math.h>

#define HW 16384

// ---------------- helpers ----------------
__device__ __forceinline__ uint32_t smem_u32(const void* p) {
    uint32_t a;
    asm("{ .reg .u64 t; cvta.to.shared.u64 t, %1; cvt.u32.u64 %0, t; }" : "=r"(a) : "l"(p));
    return a;
}
__device__ __forceinline__ void cp_async16(uint32_t dst, const void* src) {
    asm volatile("cp.async.cg.shared.global [%0], [%1], 16;" :: "r"(dst), "l"(src));
}
#define CP_COMMIT() asm volatile("cp.async.commit_group;" ::: "memory")
#define CP_WAIT0()  asm volatile("cp.async.wait_group 0;" ::: "memory")
#define CP_WAIT1()  asm volatile("cp.async.wait_group 1;" ::: "memory")

__device__ __forceinline__ uint32_t bf16x2_pack(float lo, float hi) {
    uint32_t r;
    asm("cvt.rn.bf16x2.f32 %0, %1, %2;" : "=r"(r) : "f"(hi), "f"(lo));
    return r;
}
__device__ __forceinline__ void ldmatrix_x4_trans(uint32_t* r, uint32_t addr) {
    asm volatile("ldmatrix.sync.aligned.m8n8.x4.trans.shared.b16 {%0,%1,%2,%3}, [%4];"
                 : "=r"(r[0]), "=r"(r[1]), "=r"(r[2]), "=r"(r[3]) : "r"(addr));
}
__device__ __forceinline__ void mma_bf16(float* d, const uint32_t* a, uint32_t b0, uint32_t b1) {
    asm("mma.sync.aligned.m16n8k16.row.col.f32.bf16.bf16.f32 "
        "{%0,%1,%2,%3},{%4,%5,%6,%7},{%8,%9},{%0,%1,%2,%3};"
        : "+f"(d[0]), "+f"(d[1]), "+f"(d[2]), "+f"(d[3])
        : "r"(a[0]), "r"(a[1]), "r"(a[2]), "r"(a[3]), "r"(b0), "r"(b1));
}

// ---------------- scratch (float units; bf16 tensors use 2 elems/float slot) --------
#define OFF_XS     0ULL           // bf16 [2,192,HW]
#define OFF_T1     3145728ULL     // bf16 [2,192,HW]
#define OFF_Q      6291456ULL     // bf16 [2,192,HW]
#define OFF_KVP    9437184ULL     // bf16 [2,384,HW]
#define OFF_KVB    15728640ULL    // bf16 [2,384,HW]
#define OFF_YP     22020096ULL    // bf16 [2,768,HW]
#define OFF_M1     34603008ULL
#define OFF_MF     34603392ULL
#define OFF_RQ     34603776ULL
#define OFF_RK     34604160ULL
#define OFF_SP     34604544ULL    // fp32 [2,6,8,32,32]
#define OFF_ATT    34702848ULL    // fp32 [2,6,32,32]
#define OFF_WQ     34715136ULL    // u32 13824
#define OFF_WKV    34728960ULL    // u32 9216
#define OFF_WPO    34738176ULL    // u32 18432
#define OFF_WPIN   34756608ULL    // u32 73728
#define OFF_WPOUT  34830336ULL    // u32 36864
#define OFF_PAD    34867200ULL
#define SCRATCH_TOTAL 34867264ULL
__device__ float g_scratch[SCRATCH_TOTAL];

// ---------------- prep: per-batch channel multipliers + k_v tail --------------------
__global__ void prep_kernel(const float* __restrict__ kv, const float* __restrict__ wkR,
                            const float* __restrict__ wkI, const float* __restrict__ wffk,
                            float* __restrict__ m1, float* __restrict__ mf,
                            float* __restrict__ out_tail, int tail) {
    int t = blockIdx.x * blockDim.x + threadIdx.x;
    if (t < 384) {
        int b = t / 192, c = t % 192;
        float acc = 1.0f;
        if (c < 144) {
            const float* w = wkR + c * 192; const float* v = kv + b * 256;
            for (int i = 0; i < 192; i++) acc += w[i] * v[i];
        } else {
            const float* w = wkI + (c - 144) * 64; const float* v = kv + b * 256 + 192;
            for (int i = 0; i < 64; i++) acc += w[i] * v[i];
        }
        m1[t] = acc;
    } else if (t < 768) {
        int u = t - 384; int b = u / 192, c = u % 192;
        float acc = 1.0f;
        const float* w = wffk + c * 256; const float* v = kv + b * 256;
        for (int i = 0; i < 256; i++) acc += w[i] * v[i];
        mf[u] = acc;
    } else if (t - 768 < tail) {
        out_tail[t - 768] = kv[t - 768];
    }
}

// ------- pack weights W[oc][ic] into bf16 A-fragment order (u32 = bf16x2) -----------
// u32 idx: reg=idx&3, lane=(idx>>2)&31, mi=(idx>>7)&3, kc=(idx>>9)%NKC, ocb=(idx>>9)/NKC
// oc = ocb*64 + mi*16 + g + (reg&1)*8 ; k = kc*16 + tig*2 + (reg>>1)*8, pair {k, k+1}
__device__ __forceinline__ void pack_one(const float* __restrict__ W, int ic, int NKC,
                                         uint32_t* __restrict__ pack, int idx) {
    int reg = idx & 3, lane = (idx >> 2) & 31, mi = (idx >> 7) & 3;
    int kc = (idx >> 9) % NKC, ocb = (idx >> 9) / NKC;
    int g = lane >> 2, tig = lane & 3;
    int oc = ocb * 64 + mi * 16 + g + (reg & 1) * 8;
    int k = kc * 16 + tig * 2 + (reg >> 1) * 8;
    pack[idx] = bf16x2_pack(W[(size_t)oc * ic + k], W[(size_t)oc * ic + k + 1]);
}

__global__ void wpack_all_kernel(const float* __restrict__ wq, const float* __restrict__ wkv,
                                 const float* __restrict__ wpo, const float* __restrict__ wpin,
                                 const float* __restrict__ wpout,
                                 uint32_t* __restrict__ pq, uint32_t* __restrict__ pkv,
                                 uint32_t* __restrict__ ppo, uint32_t* __restrict__ ppin,
                                 uint32_t* __restrict__ ppout) {
    int idx = blockIdx.x * 256 + threadIdx.x;
    if (idx < 13824)        pack_one(wq,    144,  9, pq,    idx);
    else if (idx < 23040)   pack_one(wkv,    48,  3, pkv,   idx - 13824);
    else if (idx < 41472)   pack_one(wpo,   192, 12, ppo,   idx - 23040);
    else if (idx < 115200)  pack_one(wpin,  192, 12, ppin,  idx - 41472);
    else if (idx < 152064)  pack_one(wpout, 384, 24, ppout, idx - 115200);
}

__global__ void pad_kernel(float* __restrict__ p) {
    if (threadIdx.x == 0) p[blockIdx.x] = 0.f;
}

// ------- channel LayerNorm * per-(b,c) multiplier -> bf16 --------------------------
__global__ void ln_scale_kernel(const float* __restrict__ x, const float* __restrict__ w,
                                const float* __restrict__ bias, const float* __restrict__ m,
                                __nv_bfloat16* __restrict__ out) {
    int p = blockIdx.x * blockDim.x + threadIdx.x;
    int b = p >> 14, px = p & (HW - 1);
    const float* xb = x + (size_t)b * 192 * HW + px;
    float s = 0.f, s2 = 0.f;
    #pragma unroll 8
    for (int c = 0; c < 192; c++) { float v = xb[(size_t)c * HW]; s += v; s2 += v * v; }
    float mu = s * (1.0f / 192.0f);
    float rstd = rsqrtf(s2 * (1.0f / 192.0f) - mu * mu + 1e-5f);
    __nv_bfloat16* ob = out + (size_t)b * 192 * HW + px;
    const float* mb = m + b * 192;
    #pragma unroll 8
    for (int c = 0; c < 192; c++) {
        float v = (xb[(size_t)c * HW] - mu) * rstd * w[c] + bias[c];
        ob[(size_t)c * HW] = __float2bfloat16(v * mb[c]);
    }
}

// ------- bf16 mma.sync conv1x1, warp-autonomous: D[oc,px] = W[oc,K] @ In[K,px] -------
// block 256px x 64oc; warp 32px x 64oc; weights=A (prepacked), pixels=B (ldmatrix.trans)
__global__ void __launch_bounds__(256) conv_mma_kernel(
        const __nv_bfloat16* __restrict__ in, int ictot, int icoff, int NKC,
        const uint32_t* __restrict__ wpack, int octot, int tpc,
        const float* __restrict__ res, float* __restrict__ outf,
        __nv_bfloat16* __restrict__ outb) {
    extern __shared__ char sm[];
    // [0, NKC*2048): packed weights ; [NKC*2048, +16KB): 8 warps x 2 x (16k x 32px bf16)
    char* sIn = sm + NKC * 2048;
    int tid = threadIdx.x, wid = tid >> 5, lane = tid & 31;
    int g = lane >> 2, tig = lane & 3;
    int ocbase = blockIdx.y * 64;

    {   // resident packed A-weights for this 64-oc slice
        const uint4* gw = (const uint4*)(wpack + (size_t)blockIdx.y * NKC * 512);
        uint4* sw4 = (uint4*)sm;
        for (int i = tid; i < NKC * 128; i += 256) sw4[i] = gw[i];
    }
    __syncthreads();

    uint32_t wInb = smem_u32(sIn) + (uint32_t)wid * 2048u;
    // ldmatrix lane address precompute (k row + px-half offsets)
    int lm = lane >> 3, lr = lane & 7;
    uint32_t lmrow = (uint32_t)(((lm & 1) * 8 + lr) * 64 + (lm >> 1) * 16);

    for (int t = 0; t < tpc; t++) {
        int pxg = (blockIdx.x * tpc + t) * 256;
        int b = pxg >> 14, pxb = pxg & (HW - 1);
        const __nv_bfloat16* gin = in + ((size_t)b * ictot + icoff) * HW + pxb + wid * 32;

        // prefetch chunk 0 -> buf 0 (warp-private): 16 rows x 64B
        #pragma unroll
        for (int i = 0; i < 2; i++) {
            int u = lane + 32 * i;
            int r = u >> 2, c = u & 3;
            cp_async16(wInb + (uint32_t)(r * 64 + c * 16), gin + (size_t)r * HW + c * 8);
        }
        CP_COMMIT();

        float d[4][4][4];
        #pragma unroll
        for (int mi = 0; mi < 4; mi++)
            #pragma unroll
            for (int ni = 0; ni < 4; ni++)
                #pragma unroll
                for (int r = 0; r < 4; r++) d[mi][ni][r] = 0.f;

        for (int kc = 0; kc < NKC; kc++) {
            if (kc + 1 < NKC) {
                const __nv_bfloat16* src = gin + (size_t)(kc + 1) * 16 * HW;
                uint32_t dstb = wInb + (uint32_t)((kc + 1) & 1) * 1024u;
                #pragma unroll
                for (int i = 0; i < 2; i++) {
                    int u = lane + 32 * i;
                    int r = u >> 2, c = u & 3;
                    cp_async16(dstb + (uint32_t)(r * 64 + c * 16), src + (size_t)r * HW + c * 8);
                }
                CP_COMMIT();
                CP_WAIT1();
            } else {
                CP_WAIT0();
            }
            __syncwarp();

            uint32_t bufb = wInb + (uint32_t)(kc & 1) * 1024u;
            uint32_t bfr[2][4];
            ldmatrix_x4_trans(bfr[0], bufb + lmrow);        // px 0-15
            ldmatrix_x4_trans(bfr[1], bufb + lmrow + 32);   // px 16-31

            const uint4* wk = (const uint4*)(sm + kc * 2048);
            #pragma unroll
            for (int mi = 0; mi < 4; mi++) {
                uint4 av4 = wk[mi * 32 + lane];
                uint32_t a[4] = {av4.x, av4.y, av4.z, av4.w};
                mma_bf16(d[mi][0], a, bfr[0][0], bfr[0][1]);
                mma_bf16(d[mi][1], a, bfr[0][2], bfr[0][3]);
                mma_bf16(d[mi][2], a, bfr[1][0], bfr[1][1]);
                mma_bf16(d[mi][3], a, bfr[1][2], bfr[1][3]);
            }
        }

        // epilogue: d[mi][ni]: c0,c1=(oc g, px 2tig,2tig+1); c2,c3=(oc g+8, same px)
        #pragma unroll
        for (int mi = 0; mi < 4; mi++) {
            int oc0 = ocbase + mi * 16 + g;
            #pragma unroll
            for (int ni = 0; ni < 4; ni++) {
                int px0 = pxb + wid * 32 + ni * 8 + tig * 2;
                size_t o0 = ((size_t)b * octot + oc0) * HW + px0;
                size_t o2 = o0 + (size_t)8 * HW;
                float v0 = d[mi][ni][0], v1 = d[mi][ni][1];
                float v2 = d[mi][ni][2], v3 = d[mi][ni][3];
                if (outf) {
                    if (res) {
                        float2 e0 = *(const float2*)(res + o0);
                        float2 e2 = *(const float2*)(res + o2);
                        v0 += e0.x; v1 += e0.y; v2 += e2.x; v3 += e2.y;
                    }
                    *(float2*)(outf + o0) = make_float2(v0, v1);
                    *(float2*)(outf + o2) = make_float2(v2, v3);
                } else {
                    *(uint32_t*)(outb + o0) = bf16x2_pack(v0, v1);
                    *(uint32_t*)(outb + o2) = bf16x2_pack(v2, v3);
                }
            }
        }
    }
}

// ---------------- depthwise 3x3, zero pad, bf16 io ----------------------------------
__global__ void dwconv_kernel(const __nv_bfloat16* __restrict__ in,
                              const float* __restrict__ w, int C,
                              __nv_bfloat16* __restrict__ out) {
    size_t idx = (size_t)blockIdx.x * blockDim.x + threadIdx.x;
    if (idx >= (size_t)2 * C * HW) return;
    int x = (int)(idx & 127);
    int y = (int)((idx >> 7) & 127);
    int c = (int)((idx >> 14) % C);
    const float* wp = w + c * 9;
    const __nv_bfloat16* ip = in + (idx - (idx & (HW - 1)));
    float acc = 0.f;
    #pragma unroll
    for (int ky = 0; ky < 3; ky++) {
        int yy = y + ky - 1;
        if (yy < 0 || yy > 127) continue;
        #pragma unroll
        for (int kx = 0; kx < 3; kx++) {
            int xx = x + kx - 1;
            if (xx < 0 || xx > 127) continue;
            acc += __bfloat162float(ip[yy * 128 + xx]) * wp[ky * 3 + kx];
        }
    }
    out[idx] = __float2bfloat16(acc);
}

// --------- fused depthwise 3x3 (768ch) + gelu gate, bf16 io ------------------------
__global__ void dwconv_gelu_kernel(const __nv_bfloat16* __restrict__ in,
                                   const float* __restrict__ w,
                                   __nv_bfloat16* __restrict__ out) {
    size_t idx = (size_t)blockIdx.x * blockDim.x + threadIdx.x;
    if (idx >= (size_t)2 * 384 * HW) return;
    int x = (int)(idx & 127);
    int y = (int)((idx >> 7) & 127);
    int c = (int)((idx >> 14) % 384);
    int b = (int)(idx / ((size_t)384 * HW));
    const __nv_bfloat16* ip1 = in + ((size_t)b * 768 + c) * HW;
    const __nv_bfloat16* ip2 = ip1 + (size_t)384 * HW;
    const float* w1 = w + c * 9;
    const float* w2 = w + (c + 384) * 9;
    float a1 = 0.f, a2 = 0.f;
    #pragma unroll
    for (int ky = 0; ky < 3; ky++) {
        int yy = y + ky - 1;
        if (yy < 0 || yy > 127) continue;
        #pragma unroll
        for (int kx = 0; kx < 3; kx++) {
            int xx = x + kx - 1;
            if (xx < 0 || xx > 127) continue;
            a1 += __bfloat162float(ip1[yy * 128 + xx]) * w1[ky * 3 + kx];
            a2 += __bfloat162float(ip2[yy * 128 + xx]) * w2[ky * 3 + kx];
        }
    }
    float ge = 0.5f * a1 * (1.0f + erff(a1 * 0.70710678118654752f));
    out[idx] = __float2bfloat16(ge * a2);
}

// ---------------- reciprocal L2 norm over HW per (b, channel), bf16 in --------------
__global__ void rnorm_kernel(const __nv_bfloat16* __restrict__ t, int chtot, int coff,
                             float* __restrict__ rn) {
    int row = blockIdx.x;
    int b = row / 192, c = row % 192;
    const __nv_bfloat16* p = t + ((size_t)b * chtot + coff + c) * HW;
    float s = 0.f;
    for (int i = threadIdx.x; i < HW; i += blockDim.x) {
        float v = __bfloat162float(p[i]); s += v * v;
    }
    __shared__ float red[8];
    #pragma unroll
    for (int o = 16; o; o >>= 1) s += __shfl_down_sync(0xffffffffu, s, o);
    if ((threadIdx.x & 31) == 0) red[threadIdx.x >> 5] = s;
    __syncthreads();
    if (threadIdx.x < 32) {
        s = (threadIdx.x < 8) ? red[threadIdx.x] : 0.f;
        #pragma unroll
        for (int o = 4; o; o >>= 1) s += __shfl_down_sync(0xffffffffu, s, o);
        if (threadIdx.x == 0) rn[row] = 1.0f / fmaxf(sqrtf(s), 1e-12f);
    }
}

// ---------------- q@k^T partials, bf16 in -------------------------------------------
__global__ void qk_kernel(const __nv_bfloat16* __restrict__ q,
                          const __nv_bfloat16* __restrict__ kv,
                          float* __restrict__ Sp) {
    int pc = blockIdx.x, hh = blockIdx.y, b = blockIdx.z;
    const __nv_bfloat16* qb = q  + ((size_t)b * 192 + hh * 32) * HW + pc * 2048;
    const __nv_bfloat16* kb = kv + ((size_t)b * 384 + hh * 32) * HW + pc * 2048;
    __shared__ float sq[32 * 33];
    __shared__ float sk[32 * 33];
    int t = threadIdx.x;
    int i = t & 31, jg = t >> 5;
    float acc[4] = {0.f, 0.f, 0.f, 0.f};
    for (int p0 = 0; p0 < 2048; p0 += 32) {
        #pragma unroll
        for (int l = 0; l < 4; l++) {
            int idx = t + l * 256;
            int r = idx >> 5, cc = idx & 31;
            sq[r * 33 + cc] = __bfloat162float(qb[(size_t)r * HW + p0 + cc]);
            sk[r * 33 + cc] = __bfloat162float(kb[(size_t)r * HW + p0 + cc]);
        }
        __syncthreads();
        #pragma unroll
        for (int p = 0; p < 32; p++) {
            float a = sq[i * 33 + p];
            #pragma unroll
            for (int j = 0; j < 4; j++) acc[j] += a * sk[(jg * 4 + j) * 33 + p];
        }
        __syncthreads();
    }
    float* sp = Sp + (((size_t)(b * 6 + hh) * 8 + pc) * 1024);
    #pragma unroll
    for (int j = 0; j < 4; j++) sp[i * 32 + jg * 4 + j] = acc[j];
}

// ---------------- softmax ------------------------------------------------------------
__global__ void softmax_kernel(const float* __restrict__ Sp, const float* __restrict__ rq,
                               const float* __restrict__ rk, const float* __restrict__ temp,
                               float* __restrict__ attn) {
    int bh = blockIdx.x;
    int b = bh / 6, hh = bh % 6;
    int t = threadIdx.x;
    int i = t >> 5, j = t & 31;
    const float* sp = Sp + (size_t)bh * 8192 + i * 32 + j;
    float s = 0.f;
    #pragma unroll
    for (int pc = 0; pc < 8; pc++) s += sp[pc * 1024];
    s *= rq[b * 192 + hh * 32 + i] * rk[b * 192 + hh * 32 + j] * temp[hh];
    float mx = s;
    #pragma unroll
    for (int o = 16; o; o >>= 1) mx = fmaxf(mx, __shfl_xor_sync(0xffffffffu, mx, o));
    float e = expf(s - mx);
    float sum = e;
    #pragma unroll
    for (int o = 16; o; o >>= 1) sum += __shfl_xor_sync(0xffffffffu, sum, o);
    attn[(size_t)bh * 1024 + i * 32 + j] = e / sum;
}

// ---------------- out = attn @ v, bf16 v in, bf16 out --------------------------------
__global__ void av_kernel(const float* __restrict__ attn,
                          const __nv_bfloat16* __restrict__ kv,
                          __nv_bfloat16* __restrict__ out) {
    int b = blockIdx.z, hh = blockIdx.y;
    int p = blockIdx.x * 256 + threadIdx.x;
    __shared__ float sA[1024];
    for (int l = threadIdx.x; l < 1024; l += 256)
        sA[l] = attn[(size_t)(b * 6 + hh) * 1024 + l];
    __syncthreads();
    const __nv_bfloat16* vb = kv + ((size_t)b * 384 + 192 + hh * 32) * HW + p;
    float v[32];
    #pragma unroll
    for (int e = 0; e < 32; e++) v[e] = __bfloat162float(vb[(size_t)e * HW]);
    __nv_bfloat16* ob = out + ((size_t)b * 192 + hh * 32) * HW + p;
    #pragma unroll
    for (int i = 0; i < 32; i++) {
        float acc = 0.f;
        #pragma unroll
        for (int e = 0; e < 32; e++) acc += sA[i * 32 + e] * v[e];
        ob[(size_t)i * HW] = __float2bfloat16(acc);
    }
}

// ====================================================================================
extern "C" void kernel_launch(void* const* d_in, const int* in_sizes, int n_in,
                              void* d_out, int out_size) {
    const float* x      = (const float*)d_in[0];
    const float* k_v    = (const float*)d_in[1];
    const float* ln1_w  = (const float*)d_in[2];
    const float* ln1_b  = (const float*)d_in[3];
    const float* temp   = (const float*)d_in[4];
    const float* w_kR   = (const float*)d_in[5];
    const float* w_kI   = (const float*)d_in[6];
    const float* w_qR   = (const float*)d_in[7];
    const float* w_qdw  = (const float*)d_in[8];
    const float* w_kvI  = (const float*)d_in[9];
    const float* w_kvdw = (const float*)d_in[10];
    const float* w_po   = (const float*)d_in[11];
    const float* ln2_w  = (const float*)d_in[12];
    const float* ln2_b  = (const float*)d_in[13];
    const float* w_ffk  = (const float*)d_in[14];
    const float* w_pin  = (const float*)d_in[15];
    const float* w_dw   = (const float*)d_in[16];
    const float* w_pout = (const float*)d_in[17];
    float* out = (float*)d_out;

    float* sc = nullptr;
    cudaGetSymbolAddress((void**)&sc, g_scratch);
    __nv_bfloat16* xs  = (__nv_bfloat16*)(sc + OFF_XS);
    __nv_bfloat16* t1  = (__nv_bfloat16*)(sc + OFF_T1);
    __nv_bfloat16* q   = (__nv_bfloat16*)(sc + OFF_Q);
    __nv_bfloat16* kvp = (__nv_bfloat16*)(sc + OFF_KVP);
    __nv_bfloat16* kvb = (__nv_bfloat16*)(sc + OFF_KVB);
    __nv_bfloat16* yp  = (__nv_bfloat16*)(sc + OFF_YP);
    float* m1  = sc + OFF_M1;
    float* mf  = sc + OFF_MF;
    float* rq  = sc + OFF_RQ;
    float* rk  = sc + OFF_RK;
    float* Sp  = sc + OFF_SP;
    float* att = sc + OFF_ATT;
    uint32_t* wq    = (uint32_t*)(sc + OFF_WQ);
    uint32_t* wkv   = (uint32_t*)(sc + OFF_WKV);
    uint32_t* wpo   = (uint32_t*)(sc + OFF_WPO);
    uint32_t* wpin  = (uint32_t*)(sc + OFF_WPIN);
    uint32_t* wpout = (uint32_t*)(sc + OFF_WPOUT);
    float* padt = sc + OFF_PAD;

    cudaFuncSetAttribute(conv_mma_kernel, cudaFuncAttributeMaxDynamicSharedMemorySize, 66560);
    auto smb = [](int NKC) { return (size_t)NKC * 2048 + 16384; };

    int tail = out_size - 6291456;
    if (tail < 0) tail = 0;
    if (tail > 512) tail = 512;

    // prep, packed weights, LN1, pad (ncu -s 5 lands on a conv)
    prep_kernel<<<5, 256>>>(k_v, w_kR, w_kI, w_ffk, m1, mf, out + 6291456, tail);
    wpack_all_kernel<<<594, 256>>>(w_qR, w_kvI, w_po, w_pin, w_pout,
                                   wq, wkv, wpo, wpin, wpout);
    ln_scale_kernel<<<128, 256>>>(x, ln1_w, ln1_b, m1, xs);
    pad_kernel<<<1, 32>>>(padt);

    // attention branch
    conv_mma_kernel<<<dim3(64, 3), 256, smb(9)>>>(xs, 192, 0, 9, wq, 192, 2,
                                                  nullptr, nullptr, t1);
    conv_mma_kernel<<<dim3(64, 6), 256, smb(3)>>>(xs, 192, 144, 3, wkv, 384, 2,
                                                  nullptr, nullptr, kvp);
    dwconv_kernel<<<(2 * 192 * HW) / 256, 256>>>(t1, w_qdw, 192, q);
    dwconv_kernel<<<(2 * 384 * HW) / 256, 256>>>(kvp, w_kvdw, 384, kvb);
    rnorm_kernel<<<384, 256>>>(q, 192, 0, rq);
    rnorm_kernel<<<384, 256>>>(kvb, 384, 0, rk);
    qk_kernel<<<dim3(8, 6, 2), 256>>>(q, kvb, Sp);
    softmax_kernel<<<12, 1024>>>(Sp, rq, rk, temp, att);
    av_kernel<<<dim3(64, 6, 2), 256>>>(att, kvb, t1);
    conv_mma_kernel<<<dim3(64, 3), 256, smb(12)>>>(t1, 192, 0, 12, wpo, 192, 2,
                                                   x, out, nullptr);

    // GDFN feed-forward
    ln_scale_kernel<<<128, 256>>>(out, ln2_w, ln2_b, mf, xs);
    conv_mma_kernel<<<dim3(16, 12), 256, smb(12)>>>(xs, 192, 0, 12, wpin, 768, 8,
                                                    nullptr, nullptr, yp);
    dwconv_gelu_kernel<<<(2 * 384 * HW) / 256, 256>>>(yp, w_dw, kvp);
    conv_mma_kernel<<<dim3(64, 3), 256, smb(24)>>>(kvp, 384, 0, 24, wpout, 192, 2,
                                                   out, out, nullptr);
}